// round 3
// baseline (speedup 1.0000x reference)
#include <cuda_runtime.h>
#include <math.h>
#include <stdint.h>

// Problem constants
#define NTOK 8192
#define DIM  2048
#define FDIM 5632
#define NE   8
#define NASSIGN (NTOK * 2)

// ---------------------------------------------------------------------------
// Scratch (device globals; no dynamic allocation allowed)
// ---------------------------------------------------------------------------
__device__ int   g_cnt[NE];
__device__ int   g_off[NE];
__device__ int   g_cursor[NE];
__device__ int   g_tok_eid[NASSIGN];
__device__ float g_tok_w[NASSIGN];
__device__ int   g_slot_token[NASSIGN];
__device__ float g_slot_w[NASSIGN];
__device__ float g_probsum[NE];
__device__ float g_fraccnt[NE];
__device__ float g_hbuf[(size_t)NASSIGN * FDIM];   // 369 MB intermediate H

// ---------------------------------------------------------------------------
// Helpers
// ---------------------------------------------------------------------------
__device__ __forceinline__ uint32_t f2tf32(float x) {
    uint32_t u;
    asm("cvt.rna.tf32.f32 %0, %1;" : "=r"(u) : "f"(x));
    return u;
}

__device__ __forceinline__ void mma_tf32(float c[4], const uint32_t a[4],
                                         uint32_t b0, uint32_t b1) {
    asm volatile(
        "mma.sync.aligned.m16n8k8.row.col.f32.tf32.tf32.f32 "
        "{%0,%1,%2,%3}, {%4,%5,%6,%7}, {%8,%9}, {%0,%1,%2,%3};"
        : "+f"(c[0]), "+f"(c[1]), "+f"(c[2]), "+f"(c[3])
        : "r"(a[0]), "r"(a[1]), "r"(a[2]), "r"(a[3]), "r"(b0), "r"(b1));
}

// ---------------------------------------------------------------------------
// K0: reset per-launch accumulators (graph replays must be idempotent)
// ---------------------------------------------------------------------------
__global__ void reset_kernel() {
    int i = threadIdx.x;
    if (i < NE) { g_cnt[i] = 0; g_probsum[i] = 0.f; g_fraccnt[i] = 0.f; }
}

// ---------------------------------------------------------------------------
// K1: router — logits, softmax, top-2, counts, aux partials.  1 warp / token.
// ---------------------------------------------------------------------------
__global__ void __launch_bounds__(256) router_kernel(const float* __restrict__ x,
                                                     const float* __restrict__ rw) {
    __shared__ float s_prob[NE], s_frac[NE];
    int tid = threadIdx.x;
    if (tid < NE) { s_prob[tid] = 0.f; s_frac[tid] = 0.f; }
    __syncthreads();

    int lane = tid & 31;
    int tok  = blockIdx.x * 8 + (tid >> 5);

    float acc[NE];
#pragma unroll
    for (int e = 0; e < NE; e++) acc[e] = 0.f;

    const float* xr = x + (size_t)tok * DIM;
    for (int d = lane; d < DIM; d += 32) {
        float xv = xr[d];
#pragma unroll
        for (int e = 0; e < NE; e++) acc[e] += xv * rw[e * DIM + d];
    }
#pragma unroll
    for (int e = 0; e < NE; e++) {
#pragma unroll
        for (int o = 16; o > 0; o >>= 1)
            acc[e] += __shfl_xor_sync(0xffffffffu, acc[e], o);
    }

    if (lane == 0) {
        float mx = acc[0];
#pragma unroll
        for (int e = 1; e < NE; e++) mx = fmaxf(mx, acc[e]);
        float p[NE]; float s = 0.f;
#pragma unroll
        for (int e = 0; e < NE; e++) { p[e] = expf(acc[e] - mx); s += p[e]; }
        float inv = 1.f / s;
#pragma unroll
        for (int e = 0; e < NE; e++) p[e] *= inv;

        int e1 = 0;
#pragma unroll
        for (int e = 1; e < NE; e++) if (p[e] > p[e1]) e1 = e;   // lowest idx on ties (jax)
        int e2 = (e1 == 0) ? 1 : 0;
#pragma unroll
        for (int e = 0; e < NE; e++) if (e != e1 && p[e] > p[e2]) e2 = e;

        float wn = 1.f / (p[e1] + p[e2]);
        g_tok_eid[tok * 2]     = e1;
        g_tok_eid[tok * 2 + 1] = e2;
        g_tok_w[tok * 2]       = p[e1] * wn;
        g_tok_w[tok * 2 + 1]   = p[e2] * wn;
        atomicAdd(&g_cnt[e1], 1);
        atomicAdd(&g_cnt[e2], 1);
#pragma unroll
        for (int e = 0; e < NE; e++) atomicAdd(&s_prob[e], p[e]);
        atomicAdd(&s_frac[e1], 1.f);
        atomicAdd(&s_frac[e2], 1.f);
    }
    __syncthreads();
    if (tid < NE) {
        atomicAdd(&g_probsum[tid], s_prob[tid]);
        atomicAdd(&g_fraccnt[tid], s_frac[tid]);
    }
}

// ---------------------------------------------------------------------------
// K2: exclusive scan of counts (E=8 — single thread is fine)
// ---------------------------------------------------------------------------
__global__ void scan_kernel() {
    int off = 0;
    for (int e = 0; e < NE; e++) {
        g_off[e] = off;
        g_cursor[e] = off;
        off += g_cnt[e];
    }
}

// ---------------------------------------------------------------------------
// K3: fill per-expert slot lists
// ---------------------------------------------------------------------------
__global__ void fill_kernel() {
    int i = blockIdx.x * blockDim.x + threadIdx.x;
    if (i < NASSIGN) {
        int e = g_tok_eid[i];
        int slot = atomicAdd(&g_cursor[e], 1);
        g_slot_token[slot] = i >> 1;
        g_slot_w[slot]     = g_tok_w[i];
    }
}

// ---------------------------------------------------------------------------
// K4: fused gate/up GEMM (TF32 mma) + SiLU*up epilogue -> g_hbuf
//   Tile 64x64, K-stage 32, 256 threads (8 warps in 2x4), per-warp 32x16,
//   dual accumulators (gate + up share the A fragments).
// ---------------------------------------------------------------------------
__global__ void __launch_bounds__(256) gateup_kernel(const float* __restrict__ x,
                                                     const float* __restrict__ gate_w,
                                                     const float* __restrict__ up_w) {
    int e   = blockIdx.z;
    int cnt = g_cnt[e];
    int m0  = blockIdx.x * 64;
    if (m0 >= cnt) return;
    int n0  = blockIdx.y * 64;
    int off = g_off[e];

    __shared__ uint32_t As[64][36];
    __shared__ uint32_t Bg[64][36];
    __shared__ uint32_t Bu[64][36];

    int tid  = threadIdx.x;
    int lane = tid & 31;
    int w    = tid >> 5;
    int wm   = w & 1;          // 0..1 (m)
    int wn   = w >> 1;         // 0..3 (n)
    int gid  = lane >> 2;
    int tig  = lane & 3;

    int lr = tid >> 3;         // load row 0..31 (and +32)
    int kq = tid & 7;          // k quad 0..7

    const float* apt[2] = {nullptr, nullptr};
#pragma unroll
    for (int h = 0; h < 2; h++) {
        int m = m0 + lr + h * 32;
        if (m < cnt)
            apt[h] = x + (size_t)g_slot_token[off + m] * DIM + kq * 4;
    }
    const float* gpt[2];
    const float* upt[2];
#pragma unroll
    for (int h = 0; h < 2; h++) {
        size_t row = (size_t)e * FDIM + n0 + lr + h * 32;
        gpt[h] = gate_w + row * DIM + kq * 4;
        upt[h] = up_w   + row * DIM + kq * 4;
    }

    float cg[2][2][4], cu[2][2][4];
#pragma unroll
    for (int i = 0; i < 2; i++)
#pragma unroll
        for (int j = 0; j < 2; j++)
#pragma unroll
            for (int q = 0; q < 4; q++) { cg[i][j][q] = 0.f; cu[i][j][q] = 0.f; }

    for (int k0 = 0; k0 < DIM; k0 += 32) {
#pragma unroll
        for (int h = 0; h < 2; h++) {
            int r = lr + h * 32;
            float4 va = make_float4(0.f, 0.f, 0.f, 0.f);
            if (apt[h]) va = *(const float4*)(apt[h] + k0);
            *(uint4*)&As[r][kq * 4] =
                make_uint4(f2tf32(va.x), f2tf32(va.y), f2tf32(va.z), f2tf32(va.w));
            float4 vg = *(const float4*)(gpt[h] + k0);
            *(uint4*)&Bg[r][kq * 4] =
                make_uint4(f2tf32(vg.x), f2tf32(vg.y), f2tf32(vg.z), f2tf32(vg.w));
            float4 vu = *(const float4*)(upt[h] + k0);
            *(uint4*)&Bu[r][kq * 4] =
                make_uint4(f2tf32(vu.x), f2tf32(vu.y), f2tf32(vu.z), f2tf32(vu.w));
        }
        __syncthreads();
#pragma unroll
        for (int kk = 0; kk < 32; kk += 8) {
            uint32_t a[2][4];
#pragma unroll
            for (int mi = 0; mi < 2; mi++) {
                int r = wm * 32 + mi * 16 + gid;
                a[mi][0] = As[r][kk + tig];
                a[mi][1] = As[r + 8][kk + tig];
                a[mi][2] = As[r][kk + tig + 4];
                a[mi][3] = As[r + 8][kk + tig + 4];
            }
#pragma unroll
            for (int ni = 0; ni < 2; ni++) {
                int c = wn * 16 + ni * 8 + gid;
                uint32_t bg0 = Bg[c][kk + tig], bg1 = Bg[c][kk + tig + 4];
                uint32_t bu0 = Bu[c][kk + tig], bu1 = Bu[c][kk + tig + 4];
#pragma unroll
                for (int mi = 0; mi < 2; mi++) {
                    mma_tf32(cg[mi][ni], a[mi], bg0, bg1);
                    mma_tf32(cu[mi][ni], a[mi], bu0, bu1);
                }
            }
        }
        __syncthreads();
    }

    // Epilogue: H = silu(gate) * up
#pragma unroll
    for (int mi = 0; mi < 2; mi++) {
#pragma unroll
        for (int ni = 0; ni < 2; ni++) {
            int col = n0 + wn * 16 + ni * 8 + 2 * tig;
            int mg0 = m0 + wm * 32 + mi * 16 + gid;
            if (mg0 < cnt) {
                size_t base = (size_t)(off + mg0) * FDIM + col;
                float g0 = cg[mi][ni][0], g1 = cg[mi][ni][1];
                g_hbuf[base]     = g0 / (1.f + expf(-g0)) * cu[mi][ni][0];
                g_hbuf[base + 1] = g1 / (1.f + expf(-g1)) * cu[mi][ni][1];
            }
            int mg1 = mg0 + 8;
            if (mg1 < cnt) {
                size_t base = (size_t)(off + mg1) * FDIM + col;
                float g2 = cg[mi][ni][2], g3 = cg[mi][ni][3];
                g_hbuf[base]     = g2 / (1.f + expf(-g2)) * cu[mi][ni][2];
                g_hbuf[base + 1] = g3 / (1.f + expf(-g3)) * cu[mi][ni][3];
            }
        }
    }
}

// ---------------------------------------------------------------------------
// K5: down GEMM (TF32 mma) + weighted atomic scatter into out
// ---------------------------------------------------------------------------
__global__ void __launch_bounds__(256) down_kernel(const float* __restrict__ down_w,
                                                   float* __restrict__ out) {
    int e   = blockIdx.z;
    int cnt = g_cnt[e];
    int m0  = blockIdx.x * 64;
    if (m0 >= cnt) return;
    int n0  = blockIdx.y * 64;
    int off = g_off[e];

    __shared__ uint32_t As[64][36];
    __shared__ uint32_t Bd[64][36];

    int tid  = threadIdx.x;
    int lane = tid & 31;
    int w    = tid >> 5;
    int wm   = w & 1;
    int wn   = w >> 1;
    int gid  = lane >> 2;
    int tig  = lane & 3;

    int lr = tid >> 3;
    int kq = tid & 7;

    const float* apt[2] = {nullptr, nullptr};
#pragma unroll
    for (int h = 0; h < 2; h++) {
        int m = m0 + lr + h * 32;
        if (m < cnt)
            apt[h] = g_hbuf + (size_t)(off + m) * FDIM + kq * 4;
    }
    const float* dpt[2];
#pragma unroll
    for (int h = 0; h < 2; h++) {
        size_t row = (size_t)e * DIM + n0 + lr + h * 32;
        dpt[h] = down_w + row * FDIM + kq * 4;
    }

    float cc[2][2][4];
#pragma unroll
    for (int i = 0; i < 2; i++)
#pragma unroll
        for (int j = 0; j < 2; j++)
#pragma unroll
            for (int q = 0; q < 4; q++) cc[i][j][q] = 0.f;

    for (int k0 = 0; k0 < FDIM; k0 += 32) {
#pragma unroll
        for (int h = 0; h < 2; h++) {
            int r = lr + h * 32;
            float4 va = make_float4(0.f, 0.f, 0.f, 0.f);
            if (apt[h]) va = *(const float4*)(apt[h] + k0);
            *(uint4*)&As[r][kq * 4] =
                make_uint4(f2tf32(va.x), f2tf32(va.y), f2tf32(va.z), f2tf32(va.w));
            float4 vd = *(const float4*)(dpt[h] + k0);
            *(uint4*)&Bd[r][kq * 4] =
                make_uint4(f2tf32(vd.x), f2tf32(vd.y), f2tf32(vd.z), f2tf32(vd.w));
        }
        __syncthreads();
#pragma unroll
        for (int kk = 0; kk < 32; kk += 8) {
            uint32_t a[2][4];
#pragma unroll
            for (int mi = 0; mi < 2; mi++) {
                int r = wm * 32 + mi * 16 + gid;
                a[mi][0] = As[r][kk + tig];
                a[mi][1] = As[r + 8][kk + tig];
                a[mi][2] = As[r][kk + tig + 4];
                a[mi][3] = As[r + 8][kk + tig + 4];
            }
#pragma unroll
            for (int ni = 0; ni < 2; ni++) {
                int c = wn * 16 + ni * 8 + gid;
                uint32_t b0 = Bd[c][kk + tig], b1 = Bd[c][kk + tig + 4];
#pragma unroll
                for (int mi = 0; mi < 2; mi++)
                    mma_tf32(cc[mi][ni], a[mi], b0, b1);
            }
        }
        __syncthreads();
    }

#pragma unroll
    for (int mi = 0; mi < 2; mi++) {
#pragma unroll
        for (int ni = 0; ni < 2; ni++) {
            int col = n0 + wn * 16 + ni * 8 + 2 * tig;
            int mg0 = m0 + wm * 32 + mi * 16 + gid;
            if (mg0 < cnt) {
                int s = off + mg0;
                int tok = g_slot_token[s];
                float wgt = g_slot_w[s];
                float* o = out + (size_t)tok * DIM + col;
                atomicAdd(o,     wgt * cc[mi][ni][0]);
                atomicAdd(o + 1, wgt * cc[mi][ni][1]);
            }
            int mg1 = mg0 + 8;
            if (mg1 < cnt) {
                int s = off + mg1;
                int tok = g_slot_token[s];
                float wgt = g_slot_w[s];
                float* o = out + (size_t)tok * DIM + col;
                atomicAdd(o,     wgt * cc[mi][ni][2]);
                atomicAdd(o + 1, wgt * cc[mi][ni][3]);
            }
        }
    }
}

// ---------------------------------------------------------------------------
// K6: aux loss scalar
// ---------------------------------------------------------------------------
__global__ void aux_kernel(float* o) {
    float a = 0.f;
    for (int e = 0; e < NE; e++)
        a += (g_probsum[e] / (float)NTOK) * (g_fraccnt[e] / (float)NTOK);
    *o = (float)NE * a;
}

// ---------------------------------------------------------------------------
// Entry
// ---------------------------------------------------------------------------
extern "C" void kernel_launch(void* const* d_in, const int* in_sizes, int n_in,
                              void* d_out, int out_size) {
    const float* x  = (const float*)d_in[0];   // [B,T,D]
    const float* rw = (const float*)d_in[1];   // [E,D]
    const float* gw = (const float*)d_in[2];   // [E,F,D]
    const float* uw = (const float*)d_in[3];   // [E,F,D]
    const float* dw = (const float*)d_in[4];   // [E,D,F]
    float* out = (float*)d_out;

    cudaMemsetAsync(out, 0, (size_t)NTOK * DIM * sizeof(float), 0);
    reset_kernel<<<1, 32>>>();
    router_kernel<<<NTOK / 8, 256>>>(x, rw);
    scan_kernel<<<1, 1>>>();
    fill_kernel<<<NASSIGN / 256, 256>>>();
    // grid.x = m-tiles (fastest: consecutive blocks share B tiles in L2)
    gateup_kernel<<<dim3(128, FDIM / 64, NE), 256>>>(x, gw, uw);
    down_kernel<<<dim3(128, DIM / 64, NE), 256>>>(dw, out);
    if (out_size > NTOK * DIM)
        aux_kernel<<<1, 1>>>(out + (size_t)NTOK * DIM);
}